// round 10
// baseline (speedup 1.0000x reference)
#include <cuda_runtime.h>
#include <cuda_bf16.h>
#include <math.h>

// Problem constants
#define BB 4
#define SS 1024
#define DD 1024
#define HH 16
#define DHH 64
#define MSZ (BB * SS)  // 4096 rows

// Scratch (no cudaMalloc allowed)
__device__ float g_Q[(size_t)MSZ * DD];
__device__ float g_K[(size_t)MSZ * DD];
__device__ float g_V[(size_t)MSZ * DD];
__device__ float g_C[(size_t)MSZ * DD];
__device__ unsigned char g_mask[BB * SS];
// Pre-split bf16 planes (reused stream-ordered across GEMMs)
__device__ __nv_bfloat16 g_Ah[(size_t)MSZ * DD];
__device__ __nv_bfloat16 g_Al[(size_t)MSZ * DD];
__device__ __nv_bfloat16 g_Bh[(size_t)DD * DD];
__device__ __nv_bfloat16 g_Bl[(size_t)DD * DD];

// ----------------------------------------------------------------------------
// Mask canonicalization (verified R4)
// ----------------------------------------------------------------------------
__global__ __launch_bounds__(1024) void mask_prep_kernel(
    const unsigned char* __restrict__ m0,
    const unsigned char* __restrict__ m1)
{
    __shared__ int s_flags;
    const int t = threadIdx.x;
    if (t == 0) s_flags = 0;
    __syncthreads();

    int f1 = 0, f23 = 0;
    for (int i = t; i < BB * SS; i += 1024) {
        unsigned char a = (unsigned char)(m0[i] | m1[i]);
        int r = i & 3;
        if (a) {
            if (r == 1) f1 = 1;
            else if (r >= 2) f23 = 1;
        }
    }
    if (f1)  atomicOr(&s_flags, 1);
    if (f23) atomicOr(&s_flags, 2);
    __syncthreads();

    const int fl = s_flags;
    int code;
    if (fl & 1)      code = 0;
    else if (fl & 2) code = 1;
    else             code = 2;

    for (int i = t; i < BB * SS; i += 1024) {
        unsigned char mm;
        if (code == 0) {
            mm = (unsigned char)((m0[i] != 0) | (m1[i] != 0));
        } else if (code == 1) {
            mm = (unsigned char)((((const float*)m0)[i] != 0.f) |
                                 (((const float*)m1)[i] != 0.f));
        } else {
            mm = (unsigned char)((((const int*)m0)[i] != 0) |
                                 (((const int*)m1)[i] != 0));
        }
        g_mask[i] = mm;
    }
}

// ----------------------------------------------------------------------------
// Shared helpers
// ----------------------------------------------------------------------------
__device__ __forceinline__ void mma16816(
    float& c0, float& c1, float& c2, float& c3,
    unsigned a0, unsigned a1, unsigned a2, unsigned a3,
    unsigned b0, unsigned b1)
{
    asm volatile(
        "mma.sync.aligned.m16n8k16.row.col.f32.bf16.bf16.f32 "
        "{%0,%1,%2,%3}, {%4,%5,%6,%7}, {%8,%9}, {%0,%1,%2,%3};\n"
        : "+f"(c0), "+f"(c1), "+f"(c2), "+f"(c3)
        : "r"(a0), "r"(a1), "r"(a2), "r"(a3), "r"(b0), "r"(b1));
}

__device__ __forceinline__ void ldsm4(unsigned addr, unsigned& r0, unsigned& r1,
                                      unsigned& r2, unsigned& r3)
{
    asm volatile(
        "ldmatrix.sync.aligned.m8n8.x4.shared.b16 {%0,%1,%2,%3}, [%4];"
        : "=r"(r0), "=r"(r1), "=r"(r2), "=r"(r3) : "r"(addr));
}

__device__ __forceinline__ void cpasync16(unsigned saddr, const void* gaddr)
{
    asm volatile("cp.async.cg.shared.global [%0], [%1], 16;\n"
                 :: "r"(saddr), "l"(gaddr));
}
#define CP_COMMIT() asm volatile("cp.async.commit_group;\n" ::: "memory")
#define CP_WAIT1()  asm volatile("cp.async.wait_group 1;\n" ::: "memory")
#define CP_WAIT0()  asm volatile("cp.async.wait_group 0;\n" ::: "memory")

__device__ __forceinline__ void split2(float x, float y, unsigned& h, unsigned& l)
{
    __nv_bfloat16 hx = __float2bfloat16(x);
    __nv_bfloat16 hy = __float2bfloat16(y);
    __nv_bfloat16 lx = __float2bfloat16(x - __bfloat162float(hx));
    __nv_bfloat16 ly = __float2bfloat16(y - __bfloat162float(hy));
    __nv_bfloat162 hh; hh.x = hx; hh.y = hy;
    __nv_bfloat162 ll; ll.x = lx; ll.y = ly;
    h = *(unsigned*)&hh;
    l = *(unsigned*)&ll;
}

__device__ __forceinline__ void split1(float x, __nv_bfloat16& h, __nv_bfloat16& l)
{
    h = __float2bfloat16(x);
    l = __float2bfloat16(x - __bfloat162float(h));
}

// ----------------------------------------------------------------------------
// Split kernel: fp32 -> (hi, lo) bf16 planes. n4 = element_count / 4.
// ----------------------------------------------------------------------------
__global__ __launch_bounds__(256) void split_kernel(
    const float* __restrict__ X,
    __nv_bfloat16* __restrict__ H, __nv_bfloat16* __restrict__ L, int n4)
{
    int i = blockIdx.x * 256 + threadIdx.x;
    if (i >= n4) return;
    float4 v = ((const float4*)X)[i];
    unsigned h01, l01, h23, l23;
    split2(v.x, v.y, h01, l01);
    split2(v.z, v.w, h23, l23);
    ((uint2*)H)[i] = make_uint2(h01, h23);
    ((uint2*)L)[i] = make_uint2(l01, l23);
}

// ----------------------------------------------------------------------------
// Tensor-core GEMM v3: pre-split bf16 inputs, cp.async 2-stage pipeline,
// ldmatrix fragment loads, zero in-loop conversion.
// C[M,N] = A[M,K] @ W[N,K]^T + bias[N]  (A, W given as hi/lo bf16 planes)
// ----------------------------------------------------------------------------
#define SM_STRIDE 40                 // bf16 per smem row (80 B, conflict-free)
#define GPLANE    (128 * SM_STRIDE)
#define PLB       (GPLANE * 2)       // 10240 B per plane
#define STAGEB    (4 * PLB)          // 40960 B per stage
#define GSMEM     (2 * STAGEB)       // 81920 B

__global__ __launch_bounds__(256, 2) void gemm_mma3_kernel(
    const __nv_bfloat16* __restrict__ Ahg, const __nv_bfloat16* __restrict__ Alg,
    const __nv_bfloat16* __restrict__ Whg, const __nv_bfloat16* __restrict__ Wlg,
    const float* __restrict__ bias, float* __restrict__ C,
    int M, int N, int K)
{
    extern __shared__ __nv_bfloat16 smdyn[];

    const int tid  = threadIdx.x;
    const int bm   = blockIdx.y * 128;
    const int bn   = blockIdx.x * 128;
    const int wid  = tid >> 5;
    const int lane = tid & 31;
    const int wm   = wid & 1;
    const int wn   = wid >> 1;
    const int g    = lane >> 2;
    const int tg   = lane & 3;

    const int lm = lane >> 3;
    const int lt = lane & 7;
    unsigned smem_u32;
    {
        unsigned long long p = __cvta_generic_to_shared(smdyn);
        smem_u32 = (unsigned)p;
    }
    const unsigned aoff = ((wm * 64 + ((lm & 1) << 3) + lt) * SM_STRIDE +
                           ((lm >> 1) << 3)) * 2;
    const unsigned boff = ((wn * 32 + ((lm >> 1) << 3) + lt) * SM_STRIDE +
                           ((lm & 1) << 3)) * 2;

    // cp.async staging: 2 threads per row, 2x16B chunks each, 4 planes
    const int crow = tid >> 1;
    const int cch  = (tid & 1) * 2;

    float acc[4][4][4];
#pragma unroll
    for (int mt = 0; mt < 4; mt++)
#pragma unroll
        for (int nt = 0; nt < 4; nt++)
#pragma unroll
            for (int e = 0; e < 4; e++) acc[mt][nt][e] = 0.f;

    const __nv_bfloat16* arow_h = Ahg + (size_t)(bm + crow) * K;
    const __nv_bfloat16* arow_l = Alg + (size_t)(bm + crow) * K;
    const __nv_bfloat16* wrow_h = Whg + (size_t)(bn + crow) * K;
    const __nv_bfloat16* wrow_l = Wlg + (size_t)(bn + crow) * K;
    const unsigned srowoff = (unsigned)(crow * SM_STRIDE) * 2 + (unsigned)cch * 16;

    auto issue_stage = [&](int stage, int k0) {
        unsigned sb = smem_u32 + (unsigned)stage * STAGEB + srowoff;
        const __nv_bfloat16* g0 = arow_h + k0 + cch * 8;
        const __nv_bfloat16* g1 = arow_l + k0 + cch * 8;
        const __nv_bfloat16* g2 = wrow_h + k0 + cch * 8;
        const __nv_bfloat16* g3 = wrow_l + k0 + cch * 8;
        cpasync16(sb,               g0);
        cpasync16(sb + 16,          g0 + 8);
        cpasync16(sb + PLB,         g1);
        cpasync16(sb + PLB + 16,    g1 + 8);
        cpasync16(sb + 2 * PLB,     g2);
        cpasync16(sb + 2 * PLB + 16, g2 + 8);
        cpasync16(sb + 3 * PLB,     g3);
        cpasync16(sb + 3 * PLB + 16, g3 + 8);
    };

    issue_stage(0, 0);
    CP_COMMIT();

    const int NT = K / 32;
    for (int kt = 0; kt < NT; kt++) {
        const int cur = kt & 1;
        if (kt + 1 < NT) {
            issue_stage(cur ^ 1, (kt + 1) * 32);
            CP_COMMIT();
            CP_WAIT1();
        } else {
            CP_WAIT0();
        }
        __syncthreads();

        const unsigned sbase = smem_u32 + (unsigned)cur * STAGEB;
#pragma unroll
        for (int ks = 0; ks < 32; ks += 16) {
            unsigned bh[4][2], bl[4][2];
#pragma unroll
            for (int p = 0; p < 2; p++) {
                unsigned ad = sbase + 2 * PLB + boff +
                              (unsigned)(p * 16 * SM_STRIDE + ks) * 2;
                unsigned r0, r1, r2, r3;
                ldsm4(ad, r0, r1, r2, r3);
                bh[2 * p][0] = r0; bh[2 * p][1] = r1;
                bh[2 * p + 1][0] = r2; bh[2 * p + 1][1] = r3;
                ldsm4(ad + PLB, r0, r1, r2, r3);
                bl[2 * p][0] = r0; bl[2 * p][1] = r1;
                bl[2 * p + 1][0] = r2; bl[2 * p + 1][1] = r3;
            }
#pragma unroll
            for (int mt = 0; mt < 4; mt++) {
                unsigned ad = sbase + aoff +
                              (unsigned)(mt * 16 * SM_STRIDE + ks) * 2;
                unsigned ah0, ah1, ah2, ah3, al0, al1, al2, al3;
                ldsm4(ad, ah0, ah1, ah2, ah3);
                ldsm4(ad + PLB, al0, al1, al2, al3);
#pragma unroll
                for (int nt = 0; nt < 4; nt++) {
                    mma16816(acc[mt][nt][0], acc[mt][nt][1],
                             acc[mt][nt][2], acc[mt][nt][3],
                             ah0, ah1, ah2, ah3, bh[nt][0], bh[nt][1]);
                    mma16816(acc[mt][nt][0], acc[mt][nt][1],
                             acc[mt][nt][2], acc[mt][nt][3],
                             ah0, ah1, ah2, ah3, bl[nt][0], bl[nt][1]);
                    mma16816(acc[mt][nt][0], acc[mt][nt][1],
                             acc[mt][nt][2], acc[mt][nt][3],
                             al0, al1, al2, al3, bh[nt][0], bh[nt][1]);
                }
            }
        }
        __syncthreads();
    }

    // Epilogue: bias add + direct STG
#pragma unroll
    for (int nt = 0; nt < 4; nt++) {
        int col = bn + wn * 32 + nt * 8 + tg * 2;
        float b0 = bias[col];
        float b1 = bias[col + 1];
#pragma unroll
        for (int mt = 0; mt < 4; mt++) {
            int row = bm + wm * 64 + mt * 16 + g;
            float* p0 = C + (size_t)row * N + col;
            float* p1 = C + (size_t)(row + 8) * N + col;
            p0[0] = acc[mt][nt][0] + b0;
            p0[1] = acc[mt][nt][1] + b1;
            p1[0] = acc[mt][nt][2] + b0;
            p1[1] = acc[mt][nt][3] + b1;
        }
    }
}

// ----------------------------------------------------------------------------
// Tensor-core flash attention (verified R8) — unchanged.
// ----------------------------------------------------------------------------
#define AST 72

__global__ __launch_bounds__(256) void attn_mma_kernel()
{
    const int tid  = threadIdx.x;
    const int wid  = tid >> 5;
    const int lane = tid & 31;
    const int g    = lane >> 2;
    const int tg   = lane & 3;
    const int qb   = blockIdx.x * 128;
    const int h    = blockIdx.y;
    const int b    = blockIdx.z;
    const int hoff = h * DHH;
    const int qrow0 = qb + wid * 16;

    __shared__ __align__(16) __nv_bfloat16 Kh[64][AST], Kl[64][AST];
    __shared__ __align__(16) __nv_bfloat16 Vth[64][AST], Vtl[64][AST];
    __shared__ unsigned char smask[64];

    unsigned qh[4][4], ql[4][4];
    {
        const float* Q0 = g_Q + (size_t)(b * SS + qrow0 + g) * DD + hoff;
        const float* Q1 = g_Q + (size_t)(b * SS + qrow0 + g + 8) * DD + hoff;
#pragma unroll
        for (int ks = 0; ks < 4; ks++) {
            int d0 = ks * 16 + tg * 2;
            float2 f0 = *(const float2*)&Q0[d0];
            float2 f1 = *(const float2*)&Q1[d0];
            float2 f2 = *(const float2*)&Q0[d0 + 8];
            float2 f3 = *(const float2*)&Q1[d0 + 8];
            split2(f0.x, f0.y, qh[ks][0], ql[ks][0]);
            split2(f1.x, f1.y, qh[ks][1], ql[ks][1]);
            split2(f2.x, f2.y, qh[ks][2], ql[ks][2]);
            split2(f3.x, f3.y, qh[ks][3], ql[ks][3]);
        }
    }

    float out[8][4];
#pragma unroll
    for (int nt = 0; nt < 8; nt++)
#pragma unroll
        for (int e = 0; e < 4; e++) out[nt][e] = 0.f;
    float m0 = -INFINITY, m1 = -INFINITY;
    float l0 = 0.f, l1 = 0.f;

    const int krow = tid >> 2;
    const int kc4  = (tid & 3) * 16;

    for (int kt = 0; kt < SS / 64; kt++) {
        float4 kv[4], vv[4];
        const float* Kg = g_K + (size_t)(b * SS + kt * 64 + krow) * DD + hoff + kc4;
        const float* Vg = g_V + (size_t)(b * SS + kt * 64 + krow) * DD + hoff + kc4;
#pragma unroll
        for (int i = 0; i < 4; i++) {
            kv[i] = *(const float4*)&Kg[i * 4];
            vv[i] = *(const float4*)&Vg[i * 4];
        }
        __syncthreads();
#pragma unroll
        for (int i = 0; i < 4; i++) {
            float kx[4] = {kv[i].x, kv[i].y, kv[i].z, kv[i].w};
            float vx[4] = {vv[i].x, vv[i].y, vv[i].z, vv[i].w};
#pragma unroll
            for (int e = 0; e < 4; e++) {
                int d = kc4 + i * 4 + e;
                __nv_bfloat16 hh, ll;
                split1(kx[e], hh, ll);
                Kh[krow][d] = hh; Kl[krow][d] = ll;
                split1(vx[e], hh, ll);
                Vth[d][krow] = hh; Vtl[d][krow] = ll;
            }
        }
        if (tid < 64) smask[tid] = g_mask[b * SS + kt * 64 + tid];
        __syncthreads();

        float sacc[8][4];
#pragma unroll
        for (int nt = 0; nt < 8; nt++) {
#pragma unroll
            for (int e = 0; e < 4; e++) sacc[nt][e] = 0.f;
            int n = nt * 8 + g;
#pragma unroll
            for (int ks = 0; ks < 4; ks++) {
                int kc = ks * 16 + tg * 2;
                unsigned bh0 = *(const unsigned*)&Kh[n][kc];
                unsigned bh1 = *(const unsigned*)&Kh[n][kc + 8];
                unsigned bl0 = *(const unsigned*)&Kl[n][kc];
                unsigned bl1 = *(const unsigned*)&Kl[n][kc + 8];
                mma16816(sacc[nt][0], sacc[nt][1], sacc[nt][2], sacc[nt][3],
                         qh[ks][0], qh[ks][1], qh[ks][2], qh[ks][3], bh0, bh1);
                mma16816(sacc[nt][0], sacc[nt][1], sacc[nt][2], sacc[nt][3],
                         qh[ks][0], qh[ks][1], qh[ks][2], qh[ks][3], bl0, bl1);
                mma16816(sacc[nt][0], sacc[nt][1], sacc[nt][2], sacc[nt][3],
                         ql[ks][0], ql[ks][1], ql[ks][2], ql[ks][3], bh0, bh1);
            }
        }

        float tmax0 = -INFINITY, tmax1 = -INFINITY;
#pragma unroll
        for (int nt = 0; nt < 8; nt++) {
            bool msk0 = smask[nt * 8 + tg * 2] != 0;
            bool msk1 = smask[nt * 8 + tg * 2 + 1] != 0;
            sacc[nt][0] = msk0 ? -1e9f : sacc[nt][0] * 0.125f;
            sacc[nt][1] = msk1 ? -1e9f : sacc[nt][1] * 0.125f;
            sacc[nt][2] = msk0 ? -1e9f : sacc[nt][2] * 0.125f;
            sacc[nt][3] = msk1 ? -1e9f : sacc[nt][3] * 0.125f;
            tmax0 = fmaxf(tmax0, fmaxf(sacc[nt][0], sacc[nt][1]));
            tmax1 = fmaxf(tmax1, fmaxf(sacc[nt][2], sacc[nt][3]));
        }
        tmax0 = fmaxf(tmax0, __shfl_xor_sync(0xffffffffu, tmax0, 1));
        tmax0 = fmaxf(tmax0, __shfl_xor_sync(0xffffffffu, tmax0, 2));
        tmax1 = fmaxf(tmax1, __shfl_xor_sync(0xffffffffu, tmax1, 1));
        tmax1 = fmaxf(tmax1, __shfl_xor_sync(0xffffffffu, tmax1, 2));

        float mn0 = fmaxf(m0, tmax0);
        float mn1 = fmaxf(m1, tmax1);
        float corr0 = __expf(m0 - mn0);
        float corr1 = __expf(m1 - mn1);
        m0 = mn0; m1 = mn1;
        l0 *= corr0; l1 *= corr1;
#pragma unroll
        for (int nt = 0; nt < 8; nt++) {
            out[nt][0] *= corr0; out[nt][1] *= corr0;
            out[nt][2] *= corr1; out[nt][3] *= corr1;
        }

        unsigned ph[4][4], pl[4][4];
#pragma unroll
        for (int ksp = 0; ksp < 4; ksp++) {
            float p00 = __expf(sacc[2 * ksp][0] - m0);
            float p01 = __expf(sacc[2 * ksp][1] - m0);
            float p10 = __expf(sacc[2 * ksp][2] - m1);
            float p11 = __expf(sacc[2 * ksp][3] - m1);
            float p20 = __expf(sacc[2 * ksp + 1][0] - m0);
            float p21 = __expf(sacc[2 * ksp + 1][1] - m0);
            float p30 = __expf(sacc[2 * ksp + 1][2] - m1);
            float p31 = __expf(sacc[2 * ksp + 1][3] - m1);
            l0 += p00 + p01 + p20 + p21;
            l1 += p10 + p11 + p30 + p31;
            split2(p00, p01, ph[ksp][0], pl[ksp][0]);
            split2(p10, p11, ph[ksp][1], pl[ksp][1]);
            split2(p20, p21, ph[ksp][2], pl[ksp][2]);
            split2(p30, p31, ph[ksp][3], pl[ksp][3]);
        }

#pragma unroll
        for (int nt = 0; nt < 8; nt++) {
            int n = nt * 8 + g;
#pragma unroll
            for (int ksp = 0; ksp < 4; ksp++) {
                int kc = ksp * 16 + tg * 2;
                unsigned bh0 = *(const unsigned*)&Vth[n][kc];
                unsigned bh1 = *(const unsigned*)&Vth[n][kc + 8];
                unsigned bl0 = *(const unsigned*)&Vtl[n][kc];
                unsigned bl1 = *(const unsigned*)&Vtl[n][kc + 8];
                mma16816(out[nt][0], out[nt][1], out[nt][2], out[nt][3],
                         ph[ksp][0], ph[ksp][1], ph[ksp][2], ph[ksp][3], bh0, bh1);
                mma16816(out[nt][0], out[nt][1], out[nt][2], out[nt][3],
                         ph[ksp][0], ph[ksp][1], ph[ksp][2], ph[ksp][3], bl0, bl1);
                mma16816(out[nt][0], out[nt][1], out[nt][2], out[nt][3],
                         pl[ksp][0], pl[ksp][1], pl[ksp][2], pl[ksp][3], bh0, bh1);
            }
        }
    }

    l0 += __shfl_xor_sync(0xffffffffu, l0, 1);
    l0 += __shfl_xor_sync(0xffffffffu, l0, 2);
    l1 += __shfl_xor_sync(0xffffffffu, l1, 1);
    l1 += __shfl_xor_sync(0xffffffffu, l1, 2);
    const float inv0 = 1.f / l0;
    const float inv1 = 1.f / l1;

    float* O0 = g_C + (size_t)(b * SS + qrow0 + g) * DD + hoff;
    float* O1 = g_C + (size_t)(b * SS + qrow0 + g + 8) * DD + hoff;
#pragma unroll
    for (int nt = 0; nt < 8; nt++) {
        int d = nt * 8 + tg * 2;
        *(float2*)&O0[d] = make_float2(out[nt][0] * inv0, out[nt][1] * inv0);
        *(float2*)&O1[d] = make_float2(out[nt][2] * inv1, out[nt][3] * inv1);
    }
}

// ----------------------------------------------------------------------------
// Launch
// ----------------------------------------------------------------------------
extern "C" void kernel_launch(void* const* d_in, const int* in_sizes, int n_in,
                              void* d_out, int out_size)
{
    const float* v = (const float*)d_in[0];
    const float* k = (const float*)d_in[1];
    const float* q = (const float*)d_in[2];
    const unsigned char* mask   = (const unsigned char*)d_in[3];
    const unsigned char* semask = (const unsigned char*)d_in[4];
    const float* Wv = (const float*)d_in[5];
    const float* bv = (const float*)d_in[6];
    const float* Wk = (const float*)d_in[7];
    const float* bk = (const float*)d_in[8];
    const float* Wq = (const float*)d_in[9];
    const float* bq = (const float*)d_in[10];
    const float* Wm = (const float*)d_in[11];
    const float* bm = (const float*)d_in[12];

    static float* Qp = nullptr;
    static float* Kp = nullptr;
    static float* Vp = nullptr;
    static float* Cp = nullptr;
    static __nv_bfloat16 *Ahp = nullptr, *Alp = nullptr, *Bhp = nullptr, *Blp = nullptr;
    if (!Qp) {
        cudaGetSymbolAddress((void**)&Qp, g_Q);
        cudaGetSymbolAddress((void**)&Kp, g_K);
        cudaGetSymbolAddress((void**)&Vp, g_V);
        cudaGetSymbolAddress((void**)&Cp, g_C);
        cudaGetSymbolAddress((void**)&Ahp, g_Ah);
        cudaGetSymbolAddress((void**)&Alp, g_Al);
        cudaGetSymbolAddress((void**)&Bhp, g_Bh);
        cudaGetSymbolAddress((void**)&Blp, g_Bl);
        cudaFuncSetAttribute(gemm_mma3_kernel,
                             cudaFuncAttributeMaxDynamicSharedMemorySize, GSMEM);
    }

    const int nA4 = MSZ * DD / 4;   // activation elems / 4
    const int nW4 = DD * DD / 4;    // weight elems / 4

    mask_prep_kernel<<<1, 1024>>>(mask, semask);

    dim3 ggrid(DD / 128, MSZ / 128);  // (8, 32)

    split_kernel<<<nA4 / 256, 256>>>(v, Ahp, Alp, nA4);
    split_kernel<<<nW4 / 256, 256>>>(Wv, Bhp, Blp, nW4);
    gemm_mma3_kernel<<<ggrid, 256, GSMEM>>>(Ahp, Alp, Bhp, Blp, bv, Vp, MSZ, DD, DD);

    split_kernel<<<nA4 / 256, 256>>>(k, Ahp, Alp, nA4);
    split_kernel<<<nW4 / 256, 256>>>(Wk, Bhp, Blp, nW4);
    gemm_mma3_kernel<<<ggrid, 256, GSMEM>>>(Ahp, Alp, Bhp, Blp, bk, Kp, MSZ, DD, DD);

    split_kernel<<<nA4 / 256, 256>>>(q, Ahp, Alp, nA4);
    split_kernel<<<nW4 / 256, 256>>>(Wq, Bhp, Blp, nW4);
    gemm_mma3_kernel<<<ggrid, 256, GSMEM>>>(Ahp, Alp, Bhp, Blp, bq, Qp, MSZ, DD, DD);

    dim3 agrid(SS / 128, HH, BB);     // (8, 16, 4)
    attn_mma_kernel<<<agrid, 256>>>();

    split_kernel<<<nA4 / 256, 256>>>(Cp, Ahp, Alp, nA4);
    split_kernel<<<nW4 / 256, 256>>>(Wm, Bhp, Blp, nW4);
    gemm_mma3_kernel<<<ggrid, 256, GSMEM>>>(Ahp, Alp, Bhp, Blp, bm, (float*)d_out, MSZ, DD, DD);
}